// round 1
// baseline (speedup 1.0000x reference)
#include <cuda_runtime.h>

// Problem constants (fixed by the reference):
// B=16, W=256, S=512, F=768, L=4, E=256, V=50000
#define BB 16
#define WW 256
#define SS 512
#define FF 768
#define LL 4
#define EE 256
#define NW (WW - 1)

// Grid: one block per (b, w) pair = 4096 blocks, 256 threads.
//   threads   0..63 : copy the 256-float embedding row as 64 float4
//   threads 64..255 : each owns one float4 (4 floats) of the F=768 bert slice
__global__ __launch_bounds__(256, 8)
void bert_lexer_fused(
    const int* __restrict__ word_indices,   // [B, W]
    const int* __restrict__ span_starts,    // [B, W-1]
    const int* __restrict__ span_ends,      // [B, W-1]
    const float4* __restrict__ emb4,        // [V, E/4=64]
    const float4* __restrict__ layers4,     // [L, B, S, F/4=192]
    const float* __restrict__ layer_weights,// [L]
    const float* __restrict__ gamma,        // [1]
    float4* __restrict__ out4)              // [B, W, (E+F)/4=256]
{
    const int bw  = blockIdx.x;        // b*W + w
    const int b   = bw >> 8;           // W = 256
    const int w   = bw & (WW - 1);
    const int tid = threadIdx.x;

    __shared__ float sw[LL];
    __shared__ float sg;
    if (tid == 0) {
        float lw0 = layer_weights[0], lw1 = layer_weights[1];
        float lw2 = layer_weights[2], lw3 = layer_weights[3];
        float m = fmaxf(fmaxf(lw0, lw1), fmaxf(lw2, lw3));
        float e0 = __expf(lw0 - m), e1 = __expf(lw1 - m);
        float e2 = __expf(lw2 - m), e3 = __expf(lw3 - m);
        float inv = 1.0f / (e0 + e1 + e2 + e3);
        sw[0] = e0 * inv; sw[1] = e1 * inv; sw[2] = e2 * inv; sw[3] = e3 * inv;
        sg = gamma[0];
    }

    float4* __restrict__ outrow = out4 + (size_t)bw * 256;

    if (tid < 64) {
        // Embedding gather: coalesced 64x float4 = 1KB row.
        const int idx = word_indices[bw];
        outrow[tid] = emb4[(size_t)idx * 64 + tid];
    }

    __syncthreads();

    if (tid >= 64) {
        const int t = tid - 64;  // 0..191  -> float4 index within F
        float4 acc = make_float4(0.f, 0.f, 0.f, 0.f);
        if (w > 0) {
            const int si  = b * NW + (w - 1);
            const int ss  = span_starts[si];
            const int se  = span_ends[si];
            const int len = se - ss;
            if (len > 0) {
                const float w0 = sw[0], w1 = sw[1], w2 = sw[2], w3 = sw[3];
                if (len == 2) {
                    // Fast path (all spans in this problem): front-batch all 8
                    // LDG.128s for max memory-level parallelism.
                    const float4* p0 = layers4 + (((size_t)0 * BB + b) * SS + ss) * 192 + t;
                    const float4* p1 = layers4 + (((size_t)1 * BB + b) * SS + ss) * 192 + t;
                    const float4* p2 = layers4 + (((size_t)2 * BB + b) * SS + ss) * 192 + t;
                    const float4* p3 = layers4 + (((size_t)3 * BB + b) * SS + ss) * 192 + t;
                    float4 a0 = p0[0],  b0 = p0[192];
                    float4 a1 = p1[0],  b1 = p1[192];
                    float4 a2 = p2[0],  b2 = p2[192];
                    float4 a3 = p3[0],  b3 = p3[192];
                    acc.x = w0*(a0.x+b0.x) + w1*(a1.x+b1.x) + w2*(a2.x+b2.x) + w3*(a3.x+b3.x);
                    acc.y = w0*(a0.y+b0.y) + w1*(a1.y+b1.y) + w2*(a2.y+b2.y) + w3*(a3.y+b3.y);
                    acc.z = w0*(a0.z+b0.z) + w1*(a1.z+b1.z) + w2*(a2.z+b2.z) + w3*(a3.z+b3.z);
                    acc.w = w0*(a0.w+b0.w) + w1*(a1.w+b1.w) + w2*(a2.w+b2.w) + w3*(a3.w+b3.w);
                } else {
                    for (int s = ss; s < se; s++) {
                        #pragma unroll
                        for (int l = 0; l < LL; l++) {
                            float4 v = layers4[(((size_t)l * BB + b) * SS + s) * 192 + t];
                            float wl = sw[l];
                            acc.x += wl * v.x; acc.y += wl * v.y;
                            acc.z += wl * v.z; acc.w += wl * v.w;
                        }
                    }
                }
                const float sc = sg / (float)len;
                acc.x *= sc; acc.y *= sc; acc.z *= sc; acc.w *= sc;
            }
        }
        // w==0 (root) or empty span -> zeros, matching the reference.
        outrow[64 + t] = acc;
    }
}

extern "C" void kernel_launch(void* const* d_in, const int* in_sizes, int n_in,
                              void* d_out, int out_size)
{
    const int*    word_indices  = (const int*)   d_in[0];
    const int*    span_starts   = (const int*)   d_in[1];
    const int*    span_ends     = (const int*)   d_in[2];
    const float4* emb4          = (const float4*)d_in[3];
    const float4* layers4       = (const float4*)d_in[4];
    const float*  layer_weights = (const float*) d_in[5];
    const float*  gamma         = (const float*) d_in[6];
    float4*       out4          = (float4*)      d_out;

    (void)in_sizes; (void)n_in; (void)out_size;

    bert_lexer_fused<<<BB * WW, 256>>>(word_indices, span_starts, span_ends,
                                       emb4, layers4, layer_weights, gamma, out4);
}